// round 8
// baseline (speedup 1.0000x reference)
#include <cuda_runtime.h>
#include <math.h>

// Problem constants
#define Bq   64
#define Tq   256
#define Cq   2048
#define WEq  256
#define Hq   1024
#define G3q  3072
#define BK   16
#define NSPL 6          // k-splits for step GEMM (176x4, 160x2)
#define NBLK 144        // 24 n-tiles x 6 splits  (all co-resident)
#define SPT  8          // GRU steps per launch

typedef unsigned long long u64;

// ---------------- scratch (device globals) -----------------------------------
__device__ float d_X  [Tq * Bq * WEq];
__device__ float d_gi [(size_t)Tq * Bq * G3q];   // [t][b][n]
__device__ float d_H  [(Tq + 1) * Bq * Hq];      // [t][b][j]
__device__ float d_ghp[NSPL][Bq][G3q];           // [split][b][n]
__device__ float d_e  [Tq * Bq * Tq];
__device__ float d_ctx[(size_t)Tq * Bq * Hq];
__device__ int   d_words[Bq];
__device__ int   d_cnt[Tq / SPT];

// ---------------- f32x2 helpers ----------------------------------------------
__device__ __forceinline__ void ffma2(u64& d, u64 a, u64 b) {
    asm("fma.rn.f32x2 %0, %1, %2, %0;" : "+l"(d) : "l"(a), "l"(b));
}
__device__ __forceinline__ float2 u2f2(u64 v) {
    unsigned lo, hi;
    asm("mov.b64 {%0, %1}, %2;" : "=r"(lo), "=r"(hi) : "l"(v));
    return make_float2(__uint_as_float(lo), __uint_as_float(hi));
}
__device__ __forceinline__ u64 pack2(float x) {
    u64 r;
    asm("mov.b64 %0, {%1, %1};" : "=l"(r) : "f"(x));
    return r;
}

// ---------------- f32x2 GEMM (BM=64 x BN=128, TM=8 x TN=8, 128 thr) ----------
// C[m, n] (+=bias) = sum_k A[m, k] * B[n, k];  pairs along M, B un-duplicated.
template <int BM, int BN, int TM, int TN, bool BNC>
__global__ __launch_bounds__((BM / TM) * (BN / TN), 3) void gemm2_k(
    const float* __restrict__ A, const float* __restrict__ A2, int K1,
    const float* __restrict__ Bm, float* __restrict__ Cm, int K,
    int lda, int ldb, int ldc,
    long long a_bs, long long b_bs, long long c_bs,
    const float* __restrict__ bias, int accf, int mode)
{
    constexpr int THREADS = (BM / TM) * (BN / TN);
    constexpr int NTX = BN / TN;
    constexpr int NP  = TM / 2;
    constexpr int NA4 = (BM * BK) / (4 * THREADS);
    constexpr int NB4 = (BN * BK) / (4 * THREADS);
    constexpr int PA  = THREADS / BM;
    constexpr int PB  = (THREADS >= BN) ? THREADS / BN : 1;
    constexpr int KSTR = THREADS / 32;      // BNC k-row stride per pass

    __shared__ __align__(16) float As[2][BK][BM];
    __shared__ __align__(16) float Bs[2][BK][BN];

    const int tid = threadIdx.x;
    const int tx  = tid % NTX;
    const int ty  = tid / NTX;
    const int n0  = blockIdx.x * BN;
    const int m0  = blockIdx.y * BM;
    const float* Ab  = A  + (size_t)blockIdx.z * a_bs;
    const float* A2b = A2 ? (A2 + (size_t)blockIdx.z * a_bs) : nullptr;
    const float* Bb  = Bm + (size_t)blockIdx.z * b_bs;
    float*       Cb  = Cm + (size_t)blockIdx.z * c_bs;

    const int ar  = tid % BM;
    const int akc = tid / BM;
    const float* Ap  = Ab + (size_t)(m0 + ar) * lda + akc * 4;
    const float* Ap2 = A2b ? (A2b + (size_t)(m0 + ar) * lda + akc * 4) : nullptr;

    int bn = 0, bkc = 0, bkr = 0, bn4 = 0;
    const float* Bp;
    if (!BNC) {
        bn  = tid % BN;
        bkc = tid / BN;
        Bp  = Bb + (size_t)(n0 + bn) * ldb + bkc * 4;
    } else {
        bkr = tid / 32;
        bn4 = (tid & 31) * 4;
        Bp  = Bb + (size_t)bkr * ldb + n0 + bn4;
    }

    u64 acc[NP][TN];
#pragma unroll
    for (int p = 0; p < NP; p++)
#pragma unroll
        for (int j = 0; j < TN; j++) acc[p][j] = 0ull;

    float4 a_r[NA4], b_r[NB4];

    auto LOADA = [&](int kt) {
#pragma unroll
        for (int i = 0; i < NA4; i++) {
            int kcol = kt * BK + 4 * i * PA;
            const float* base = (Ap2 && (kcol + akc * 4) >= K1) ? (Ap2 - K1) : Ap;
            a_r[i] = *(const float4*)(base + kcol);
        }
    };
    auto LOADB = [&](int kt) {
        if (!BNC) {
#pragma unroll
            for (int i = 0; i < NB4; i++)
                b_r[i] = *(const float4*)(Bp + (size_t)kt * BK + 4 * i * PB);
        } else {
#pragma unroll
            for (int i = 0; i < NB4; i++)
                b_r[i] = *(const float4*)(Bp + (size_t)(kt * BK + KSTR * i) * ldb);
        }
    };
    auto STORE = [&](int buf) {
#pragma unroll
        for (int i = 0; i < NA4; i++) {
            int k4 = akc + i * PA;
            As[buf][4 * k4 + 0][ar] = a_r[i].x;
            As[buf][4 * k4 + 1][ar] = a_r[i].y;
            As[buf][4 * k4 + 2][ar] = a_r[i].z;
            As[buf][4 * k4 + 3][ar] = a_r[i].w;
        }
        if (!BNC) {
#pragma unroll
            for (int i = 0; i < NB4; i++) {
                int k4 = bkc + i * PB;
                Bs[buf][4 * k4 + 0][bn] = b_r[i].x;
                Bs[buf][4 * k4 + 1][bn] = b_r[i].y;
                Bs[buf][4 * k4 + 2][bn] = b_r[i].z;
                Bs[buf][4 * k4 + 3][bn] = b_r[i].w;
            }
        } else {
#pragma unroll
            for (int i = 0; i < NB4; i++)
                *(float4*)&Bs[buf][bkr + KSTR * i][bn4] = b_r[i];
        }
    };

    LOADA(0); LOADB(0);
    STORE(0);
    __syncthreads();

    const int nt = K / BK;
    for (int it = 0; it < nt; it++) {
        const int cur = it & 1;
        if (it + 1 < nt) { LOADA(it + 1); LOADB(it + 1); }

#pragma unroll
        for (int k = 0; k < BK; k++) {
            const float* ask = &As[cur][k][ty * TM];
            const float* bsk = &Bs[cur][k][tx];
            u64 bv[TN];
#pragma unroll
            for (int j = 0; j < TN; j++)
                bv[j] = pack2(bsk[j * NTX]);
            u64 av[NP];
#pragma unroll
            for (int p = 0; p < NP; p++)
                av[p] = *(const u64*)(ask + 2 * p);
#pragma unroll
            for (int p = 0; p < NP; p++)
#pragma unroll
                for (int j = 0; j < TN; j++)
                    ffma2(acc[p][j], av[p], bv[j]);
        }

        if (it + 1 < nt) STORE(cur ^ 1);
        __syncthreads();
    }

    float bj[TN];
#pragma unroll
    for (int j = 0; j < TN; j++)
        bj[j] = bias ? bias[n0 + j * NTX + tx] : 0.f;

#pragma unroll
    for (int p = 0; p < NP; p++) {
        int mA = m0 + ty * TM + 2 * p;
        int mB = mA + 1;
        size_t rA = (mode == 1) ? ((size_t)(mA & 63) * Tq + (mA >> 6)) : (size_t)mA;
        size_t rB = (mode == 1) ? ((size_t)(mB & 63) * Tq + (mB >> 6)) : (size_t)mB;
        float* cpa = Cb + rA * (size_t)ldc + n0;
        float* cpb = Cb + rB * (size_t)ldc + n0;
#pragma unroll
        for (int j = 0; j < TN; j++) {
            float2 f = u2f2(acc[p][j]);
            int off = j * NTX + tx;
            float va = f.x + bj[j];
            float vb = f.y + bj[j];
            if (accf) { va += cpa[off]; vb += cpb[off]; }
            cpa[off] = va;
            cpb[off] = vb;
        }
    }
}

// ============================================================================
// GRU step group: SPT timesteps per launch, 144 blocks x 128 threads.
// W_hh slice (128n x klen) staged into smem ONCE per launch; per step H_t
// slice staged once; K-loop runs with ZERO syncs (TM=8 x TN=8, 2 FLOP/B).
// Then: partial write -> grid barrier -> distributed float4 gates -> barrier.
// ============================================================================
__device__ __forceinline__ void stepbar(int* cnt, int target)
{
    __syncthreads();
    if (threadIdx.x == 0) {
        __threadfence();
        atomicAdd(cnt, 1);
        while (*(volatile int*)cnt < target) {}
        __threadfence();
    }
    __syncthreads();
}

__global__ __launch_bounds__(128, 1) void gru8_k(
    const float* __restrict__ W_hh, const float* __restrict__ b_hh, int t0)
{
    extern __shared__ float sm[];
    float* Bsm = sm;               // [klen][128], max 176*128
    float* Asm = sm + 176 * 128;   // [klen][64]

    const int tid = threadIdx.x;
    const int bx  = blockIdx.x;            // 0..23 n-tile
    const int spl = blockIdx.y;            // 0..5  k-split
    const int fbid = spl * 24 + bx;
    const int n0  = bx * 128;
    const int k0  = (spl < 4) ? spl * 176 : 704 + (spl - 4) * 160;
    const int klen = (spl < 4) ? 176 : 160;
    const int kq  = klen / 4;
    int* cnt = &d_cnt[t0 / SPT];

    // stage W_hh slice once (persistent across all SPT steps)
    {
        const float* wr = W_hh + (size_t)(n0 + tid) * Hq + k0;
        for (int c = 0; c < kq; c++) {
            float4 v = *(const float4*)(wr + 4 * c);
            Bsm[(4 * c + 0) * 128 + tid] = v.x;
            Bsm[(4 * c + 1) * 128 + tid] = v.y;
            Bsm[(4 * c + 2) * 128 + tid] = v.z;
            Bsm[(4 * c + 3) * 128 + tid] = v.w;
        }
    }

    const int ty = tid >> 4;               // 0..7  (b rows ty*8..+7)
    const int tx = tid & 15;               // n = n0 + tx + 16j

    // gates: one float4 (4 j) per thread
    const int pi = fbid * 128 + tid;       // active < 16384
    const int gb = pi >> 8;                // batch
    const int gj = (pi & 255) * 4;         // j quad base
    float4 br4, bz4, bn4v;
    if (pi < Bq * (Hq / 4)) {
        br4  = *(const float4*)(b_hh + gj);
        bz4  = *(const float4*)(b_hh + Hq + gj);
        bn4v = *(const float4*)(b_hh + 2 * Hq + gj);
    }

    for (int s = 0; s < SPT; s++) {
        const int t = t0 + s;
        const float* Ht = d_H + (size_t)t * Bq * Hq;

        __syncthreads();   // Asm reuse guard
        for (int idx = tid; idx < 64 * kq; idx += 128) {
            int b = idx / kq, c = idx % kq;
            float4 v = *(const float4*)(Ht + (size_t)b * Hq + k0 + 4 * c);
            Asm[(4 * c + 0) * 64 + b] = v.x;
            Asm[(4 * c + 1) * 64 + b] = v.y;
            Asm[(4 * c + 2) * 64 + b] = v.z;
            Asm[(4 * c + 3) * 64 + b] = v.w;
        }
        __syncthreads();

        u64 acc[4][8];
#pragma unroll
        for (int p = 0; p < 4; p++)
#pragma unroll
            for (int j = 0; j < 8; j++) acc[p][j] = 0ull;

#pragma unroll 4
        for (int k = 0; k < klen; k++) {
            const float* ask = &Asm[k * 64 + ty * 8];
            const float* bsk = &Bsm[k * 128 + tx];
            u64 bv[8];
#pragma unroll
            for (int j = 0; j < 8; j++) bv[j] = pack2(bsk[j * 16]);
            u64 av[4];
#pragma unroll
            for (int p = 0; p < 4; p++) av[p] = *(const u64*)(ask + 2 * p);
#pragma unroll
            for (int p = 0; p < 4; p++)
#pragma unroll
                for (int j = 0; j < 8; j++)
                    ffma2(acc[p][j], av[p], bv[j]);
        }

        // write partials d_ghp[spl][b][n0+...]
#pragma unroll
        for (int p = 0; p < 4; p++) {
            int bA = ty * 8 + 2 * p;
            float* cpa = &d_ghp[spl][bA][n0];
            float* cpb = &d_ghp[spl][bA + 1][n0];
#pragma unroll
            for (int j = 0; j < 8; j++) {
                float2 f = u2f2(acc[p][j]);
                int off = j * 16 + tx;
                cpa[off] = f.x;
                cpb[off] = f.y;
            }
        }

        stepbar(cnt, NBLK * (2 * s + 1));

        // ---- distributed gates: one float4 quad per thread ----
        if (pi < Bq * (Hq / 4)) {
            float4 sr = br4, sz = bz4, sn = bn4v;
#pragma unroll
            for (int sp = 0; sp < NSPL; sp++) {
                const float* q = &d_ghp[sp][gb][0];
                float4 v;
                v = __ldcg((const float4*)(q + gj));
                sr.x += v.x; sr.y += v.y; sr.z += v.z; sr.w += v.w;
                v = __ldcg((const float4*)(q + Hq + gj));
                sz.x += v.x; sz.y += v.y; sz.z += v.z; sz.w += v.w;
                v = __ldcg((const float4*)(q + 2 * Hq + gj));
                sn.x += v.x; sn.y += v.y; sn.z += v.z; sn.w += v.w;
            }
            const float* gib = d_gi + ((size_t)t * Bq + gb) * G3q;
            float4 gir = *(const float4*)(gib + gj);
            float4 giz = *(const float4*)(gib + Hq + gj);
            float4 gin = *(const float4*)(gib + 2 * Hq + gj);
            float4 hp  = __ldcg((const float4*)(Ht + (size_t)gb * Hq + gj));

            float4 hn;
            {
                float r0 = 1.f / (1.f + expf(-(gir.x + sr.x)));
                float z0 = 1.f / (1.f + expf(-(giz.x + sz.x)));
                float n0v = tanhf(gin.x + r0 * sn.x);
                hn.x = (1.f - z0) * n0v + z0 * hp.x;
                float r1 = 1.f / (1.f + expf(-(gir.y + sr.y)));
                float z1 = 1.f / (1.f + expf(-(giz.y + sz.y)));
                float n1 = tanhf(gin.y + r1 * sn.y);
                hn.y = (1.f - z1) * n1 + z1 * hp.y;
                float r2 = 1.f / (1.f + expf(-(gir.z + sr.z)));
                float z2 = 1.f / (1.f + expf(-(giz.z + sz.z)));
                float n2 = tanhf(gin.z + r2 * sn.z);
                hn.z = (1.f - z2) * n2 + z2 * hp.z;
                float r3 = 1.f / (1.f + expf(-(gir.w + sr.w)));
                float z3 = 1.f / (1.f + expf(-(giz.w + sz.w)));
                float n3 = tanhf(gin.w + r3 * sn.w);
                hn.w = (1.f - z3) * n3 + z3 * hp.w;
            }
            *(float4*)(d_H + ((size_t)(t + 1) * Bq + gb) * Hq + gj) = hn;
        }

        stepbar(cnt, NBLK * (2 * s + 2));
    }
}

// ---------------- small kernels ----------------------------------------------
__global__ void embed_k(const int* __restrict__ targets, const float* __restrict__ E)
{
    int m = blockIdx.x;                 // t*B + b
    int t = m >> 6, b = m & 63;
    int id = (t == 0) ? 0 : targets[b * Tq + (t - 1)];
    const float4* src = (const float4*)(E + (size_t)id * WEq);
    float4* dst = (float4*)(d_X + (size_t)m * WEq);
    dst[threadIdx.x] = src[threadIdx.x];
}

__global__ void words_k(const unsigned char* __restrict__ mask8)
{
    int b = blockIdx.x, t = threadIdx.x;
    int is8 = (mask8[1] != 0);
    int v;
    if (is8) v = mask8[b * Tq + t] ? 1 : 0;
    else     v = ((const int*)mask8)[b * Tq + t] ? 1 : 0;
#pragma unroll
    for (int o = 16; o; o >>= 1) v += __shfl_down_sync(0xffffffffu, v, o);
    __shared__ int red[8];
    if ((t & 31) == 0) red[t >> 5] = v;
    __syncthreads();
    if (t == 0) {
        int s = 0;
#pragma unroll
        for (int i = 0; i < 8; i++) s += red[i];
        d_words[b] = s;
    }
}

__global__ void h0_k(const float* __restrict__ enc)
{
    int b = blockIdx.x;
    const float4* src = (const float4*)(enc + ((size_t)b * Tq + (Tq - 1)) * Hq);
    float4* dst = (float4*)(d_H + (size_t)b * Hq);
    dst[threadIdx.x] = src[threadIdx.x];
}

__global__ void softmax_k()
{
    int m = blockIdx.x;                 // t*B + b
    int b = m & (Bq - 1);
    int wn = d_words[b];
    float* e = d_e + (size_t)m * Tq;
    int s = threadIdx.x;
    float v = (s < wn) ? e[s] : -3.0e38f;

    __shared__ float red[8];
    __shared__ float smax, ssum;
    float mx = v;
#pragma unroll
    for (int o = 16; o; o >>= 1) mx = fmaxf(mx, __shfl_xor_sync(0xffffffffu, mx, o));
    if ((s & 31) == 0) red[s >> 5] = mx;
    __syncthreads();
    if (s == 0) {
        float x = red[0];
#pragma unroll
        for (int i = 1; i < 8; i++) x = fmaxf(x, red[i]);
        smax = x;
    }
    __syncthreads();
    float ex = (s < wn) ? expf(v - smax) : 0.f;
    float sum = ex;
#pragma unroll
    for (int o = 16; o; o >>= 1) sum += __shfl_xor_sync(0xffffffffu, sum, o);
    if ((s & 31) == 0) red[s >> 5] = sum;
    __syncthreads();
    if (s == 0) {
        float x = 0.f;
#pragma unroll
        for (int i = 0; i < 8; i++) x += red[i];
        ssum = 1.f / x;
    }
    __syncthreads();
    e[s] = ex * ssum;
}

// ---------------- launch ------------------------------------------------------
extern "C" void kernel_launch(void* const* d_in, const int* in_sizes, int n_in,
                              void* d_out, int out_size)
{
    const float*         enc     = (const float*)d_in[0];
    const unsigned char* mask    = (const unsigned char*)d_in[1];
    const int*           targets = (const int*)d_in[2];
    const float*         E       = (const float*)d_in[3];
    const float*         W_ih    = (const float*)d_in[4];
    const float*         W_hh    = (const float*)d_in[5];
    const float*         b_ih    = (const float*)d_in[6];
    const float*         b_hh    = (const float*)d_in[7];
    const float*         W_out   = (const float*)d_in[8];
    const float*         b_out   = (const float*)d_in[9];
    float* out = (float*)d_out;

    void* p;
    cudaGetSymbolAddress(&p, d_X);   float* X   = (float*)p;
    cudaGetSymbolAddress(&p, d_gi);  float* GI  = (float*)p;
    cudaGetSymbolAddress(&p, d_H);   float* Hh  = (float*)p;
    cudaGetSymbolAddress(&p, d_e);   float* Ee  = (float*)p;
    cudaGetSymbolAddress(&p, d_ctx); float* CTX = (float*)p;
    void* cntp;
    cudaGetSymbolAddress(&cntp, d_cnt);

    static int smem_set = 0;
    if (!smem_set) {
        cudaFuncSetAttribute(gru8_k,
                             cudaFuncAttributeMaxDynamicSharedMemorySize,
                             (176 * 128 + 176 * 64) * 4);
        smem_set = 1;
    }

    // Phase 0
    cudaMemsetAsync(cntp, 0, (Tq / SPT) * sizeof(int));
    embed_k<<<Tq * Bq, 64>>>(targets, E);
    words_k<<<Bq, 256>>>(mask);
    h0_k<<<Bq, 256>>>(enc);

    // Phase 1: gi = X @ W_ih^T + b_ih   (16384 x 3072 x 256), layout [t][b][n]
    gemm2_k<64, 128, 8, 8, false><<<dim3(G3q / 128, (Tq * Bq) / 64, 1), 128>>>(
        X, nullptr, 1 << 30, W_ih, GI, WEq, WEq, WEq, G3q, 0, 0, 0, b_ih, 0, 0);

    // Phase 2: GRU recurrence — SPT steps/launch, persistent-W step kernel
    for (int t0 = 0; t0 < Tq; t0 += SPT)
        gru8_k<<<dim3(24, NSPL), 128, (176 * 128 + 176 * 64) * 4>>>(W_hh, b_hh, t0);

    // Phase 3a: e[t,b,s] = h1[t,b,:] . enc[b,s,:]
    gemm2_k<64, 128, 8, 8, false><<<dim3(Tq / 128, Tq / 64, Bq), 128>>>(
        Hh + (size_t)Bq * Hq, nullptr, 1 << 30, enc, Ee, Hq,
        Bq * Hq, Hq, Bq * Tq,
        Hq, (long long)Tq * Hq, Tq,
        nullptr, 0, 0);

    // Phase 3b: masked softmax
    softmax_k<<<Tq * Bq, Tq>>>();

    // Phase 3c: ctx[t,b,:] = alpha[t,b,:] @ enc[b]   (B n-contiguous)
    gemm2_k<64, 128, 8, 8, true><<<dim3(Hq / 128, Tq / 64, Bq), 128>>>(
        Ee, nullptr, 1 << 30, enc, CTX, Tq,
        Bq * Tq, Hq, Bq * Hq,
        Tq, (long long)Tq * Hq, Hq,
        nullptr, 0, 0);

    // Phase 4: logits = [h1 | ctx] @ W_out^T + b_out, concat K=2048, (B,T,C) out
    gemm2_k<64, 128, 8, 8, false><<<dim3(Cq / 128, (Tq * Bq) / 64, 1), 128>>>(
        Hh + (size_t)Bq * Hq, CTX, Hq, W_out, out, 2 * Hq,
        Hq, 2 * Hq, Cq, 0, 0, 0, b_out, 0, 1);
}